// round 9
// baseline (speedup 1.0000x reference)
#include <cuda_runtime.h>
#include <cuda_bf16.h>
#include <cstdint>
#include <math.h>

#define BATCH 16
#define SEQ   4096
#define D2    1024
#define H     512
#define MDIM  (BATCH*SEQ)      // 65536

// ---- GEMM tiling (int8) ----
#define KT      128            // k-tile: 128 int8 = 128B rows
#define NKT     (D2/KT)        // 8
#define TILE_M  128
#define TILE_N  128

// quantization scales
#define RANGE_A 6.0f
#define RANGE_B 0.12f
#define QA (127.0f/RANGE_A)
#define QB (127.0f/RANGE_B)
#define SAB ((RANGE_A/127.0f)*(RANGE_B/127.0f))

// per-stage smem layout (bytes): A1 A0 B1 B0, 16KB each
#define A1_OFF 0
#define A0_OFF 16384
#define B1_OFF 32768
#define B0_OFF 49152
#define STAGE_BYTES 65536
#define SMEM_ALLOC (2*STAGE_BYTES + 256)

// ---------------------------------------------------------------------------
// Device-global scratch
// ---------------------------------------------------------------------------
__device__ __align__(16) char g_A1[(size_t)MDIM * D2];   // 64MB
__device__ __align__(16) char g_A0[(size_t)MDIM * D2];   // 64MB
__device__ __align__(16) char g_B1[(size_t)H * D2];      // 512KB (W_e^T, [n][k])
__device__ __align__(16) char g_B0[(size_t)H * D2];      // 512KB
__device__ float g_c[BATCH * H];
__device__ float g_scores[BATCH * SEQ];

// ---------------------------------------------------------------------------
// PTX helpers (baseline ISA only: plain sm_103 target)
// ---------------------------------------------------------------------------
__device__ __forceinline__ uint32_t smem_u32(const void* p) {
    uint32_t a;
    asm("{ .reg .u64 t; cvta.to.shared.u64 t, %1; cvt.u32.u64 %0, t; }" : "=r"(a) : "l"(p));
    return a;
}
__device__ __forceinline__ void cpa16(uint32_t s, const void* g) {
    asm volatile("cp.async.cg.shared.global [%0], [%1], 16;" :: "r"(s), "l"(g) : "memory");
}
__device__ __forceinline__ void ldsm4(uint32_t* r, uint32_t addr) {
    asm volatile("ldmatrix.sync.aligned.m8n8.x4.shared.b16 {%0,%1,%2,%3}, [%4];"
        : "=r"(r[0]), "=r"(r[1]), "=r"(r[2]), "=r"(r[3]) : "r"(addr));
}
__device__ __forceinline__ void imma16832(int* d, const uint32_t* a,
                                          uint32_t b0, uint32_t b1) {
    asm volatile(
        "mma.sync.aligned.m16n8k32.row.col.s32.s8.s8.s32 "
        "{%0,%1,%2,%3}, {%4,%5,%6,%7}, {%8,%9}, {%0,%1,%2,%3};"
        : "+r"(d[0]), "+r"(d[1]), "+r"(d[2]), "+r"(d[3])
        : "r"(a[0]), "r"(a[1]), "r"(a[2]), "r"(a[3]), "r"(b0), "r"(b1));
}
__device__ __forceinline__ uint32_t swz(uint32_t o) { return o ^ ((o >> 3) & 0x70); }

// split x into hi/lo int8 pair: x*q ~= a1 + a0/256
__device__ __forceinline__ void qsplit(float x, float q, char& hi, char& lo) {
    float xs = fminf(fmaxf(x * q, -127.49f), 127.49f);
    float h = rintf(xs);
    float l = fminf(fmaxf(rintf((xs - h) * 256.0f), -127.0f), 127.0f);
    hi = (char)(int)h;
    lo = (char)(int)l;
}

// ---------------------------------------------------------------------------
// K_init
// ---------------------------------------------------------------------------
__global__ void k_init(float* __restrict__ out) {
    int i = blockIdx.x * blockDim.x + threadIdx.x;
    if (i < BATCH * SEQ) g_scores[i] = 0.0f;
    if (i < BATCH * D2)  out[i] = 0.0f;
}

// ---------------------------------------------------------------------------
// K_precompute: c[b,h] = hidden[b,:] . W_attn[0:D2, h] + b_attn[h]  (exact fp32)
// ---------------------------------------------------------------------------
__global__ void k_precompute(const float* __restrict__ hidden,
                             const float* __restrict__ W,
                             const float* __restrict__ bias) {
    __shared__ float sh[D2];
    int b = blockIdx.x;
    for (int i = threadIdx.x; i < D2; i += blockDim.x) sh[i] = hidden[(size_t)b * D2 + i];
    __syncthreads();
    int h = threadIdx.x;
    float acc = bias[h];
#pragma unroll 8
    for (int k = 0; k < D2; ++k) acc = fmaf(sh[k], W[(size_t)k * H + h], acc);
    g_c[b * H + h] = acc;
}

// ---------------------------------------------------------------------------
// K_convB: W_e[k][n] -> g_B1/g_B0[n][k]  (int8 hi/lo, transposed to n-major)
// ---------------------------------------------------------------------------
__global__ void k_convB(const float* __restrict__ W) {
    int idx = blockIdx.x * blockDim.x + threadIdx.x;   // H*D2
    int n = idx >> 10, k = idx & 1023;
    float x = W[(size_t)(D2 + k) * H + n];
    char hi, lo;
    qsplit(x, QB, hi, lo);
    g_B1[idx] = hi;
    g_B0[idx] = lo;
}

// ---------------------------------------------------------------------------
// K_convA: enc fp32 -> g_A1/g_A0 int8 hi/lo (row-major unchanged)
// ---------------------------------------------------------------------------
__global__ void k_convA(const float4* __restrict__ enc4) {
    size_t i = (size_t)blockIdx.x * blockDim.x + threadIdx.x;   // MDIM*D2/4
    float4 v = enc4[i];
    char h0, l0, h1, l1, h2, l2, h3, l3;
    qsplit(v.x, QA, h0, l0);
    qsplit(v.y, QA, h1, l1);
    qsplit(v.z, QA, h2, l2);
    qsplit(v.w, QA, h3, l3);
    ((char4*)g_A1)[i] = make_char4(h0, h1, h2, h3);
    ((char4*)g_A0)[i] = make_char4(l0, l1, l2, l3);
}

// ---------------------------------------------------------------------------
// K_scores: int8 3-term GEMM (IMMA 16832) + tanh + dot(w_v) epilogue.
// Grid (4, 512). 256 threads. Warps 2m x 4n, warp tile 64x32.
// ---------------------------------------------------------------------------
__device__ __forceinline__ void load_tile(uint32_t stage, int kt, int m0, int n0, int tid) {
    const size_t kOff = (size_t)kt * KT;
#pragma unroll
    for (int i = 0; i < 4; ++i) {          // A: 128 rows x 8 16B-chunks = 1024
        int c = tid + 256 * i;
        int row = c >> 3, c16 = c & 7;
        uint32_t so = swz((uint32_t)(row * 128 + c16 * 16));
        size_t e = (size_t)(m0 + row) * D2 + kOff + c16 * 16;
        cpa16(stage + A1_OFF + so, g_A1 + e);
        cpa16(stage + A0_OFF + so, g_A0 + e);
    }
#pragma unroll
    for (int i = 0; i < 4; ++i) {          // B: 128 rows x 8 chunks = 1024
        int c = tid + 256 * i;
        int row = c >> 3, c16 = c & 7;
        uint32_t so = swz((uint32_t)(row * 128 + c16 * 16));
        size_t e = (size_t)(n0 + row) * D2 + kOff + c16 * 16;
        cpa16(stage + B1_OFF + so, g_B1 + e);
        cpa16(stage + B0_OFF + so, g_B0 + e);
    }
}

__global__ void __launch_bounds__(256, 1)
k_scores(const float* __restrict__ wv) {
    extern __shared__ char smem[];
    uint32_t sb = smem_u32(smem);
    sb = (sb + 127u) & ~127u;

    const int tid = threadIdx.x;
    const int wid = tid >> 5, lane = tid & 31;
    const int warp_m = wid >> 2;          // 0..1 -> M offset *64
    const int warp_n = wid & 3;           // 0..3 -> N offset *32
    const int g = lane >> 2, t = lane & 3;

    const int n0 = blockIdx.x * TILE_N;
    const int m0 = blockIdx.y * TILE_M;

    __shared__ float s_score[TILE_M];
    if (tid < TILE_M) s_score[tid] = 0.0f;

    // ldmatrix lane addressing (byte offsets; identical to bf16 k16 pattern)
    const int a_lm = ((lane >> 3) & 1) * 8 + (lane & 7);   // m within 16
    const int a_kb = (lane >> 4) * 16;                     // k-byte within 32
    const int b_ln = (lane >> 4) * 8 + (lane & 7);         // n within 16
    const int b_kb = ((lane >> 3) & 1) * 16;

    int acc11[4][4][4];                   // P11 accumulators
    int accX [4][4][4];                   // P10 + P01 (same 1/256 scale)
#pragma unroll
    for (int mt = 0; mt < 4; mt++)
#pragma unroll
        for (int nt = 0; nt < 4; nt++)
#pragma unroll
            for (int e = 0; e < 4; e++) { acc11[mt][nt][e] = 0; accX[mt][nt][e] = 0; }

    // prologue: tile 0 -> stage 0
    load_tile(sb, 0, m0, n0, tid);
    asm volatile("cp.async.commit_group;" ::: "memory");

    for (int kt = 0; kt < NKT; ++kt) {
        const uint32_t cur = sb + (uint32_t)(kt & 1) * STAGE_BYTES;
        __syncthreads();
        if (kt + 1 < NKT) {
            load_tile(sb + (uint32_t)((kt + 1) & 1) * STAGE_BYTES, kt + 1, m0, n0, tid);
            asm volatile("cp.async.commit_group;" ::: "memory");
            asm volatile("cp.async.wait_group 1;" ::: "memory");
        } else {
            asm volatile("cp.async.wait_group 0;" ::: "memory");
        }
        __syncthreads();

#pragma unroll
        for (int ks = 0; ks < 4; ++ks) {   // 4 x k32 steps per 128-K tile
            uint32_t a1[4][4], a0[4][4], b1[2][4], b0[2][4];
#pragma unroll
            for (int mt = 0; mt < 4; mt++) {
                uint32_t off = swz((uint32_t)((warp_m * 64 + mt * 16 + a_lm) * 128
                                              + ks * 32 + a_kb));
                ldsm4(a1[mt], cur + A1_OFF + off);
                ldsm4(a0[mt], cur + A0_OFF + off);
            }
#pragma unroll
            for (int p = 0; p < 2; p++) {
                uint32_t off = swz((uint32_t)((warp_n * 32 + p * 16 + b_ln) * 128
                                              + ks * 32 + b_kb));
                ldsm4(b1[p], cur + B1_OFF + off);
                ldsm4(b0[p], cur + B0_OFF + off);
            }
            // P11: a1*b1
#pragma unroll
            for (int mt = 0; mt < 4; mt++)
#pragma unroll
                for (int nt = 0; nt < 4; nt++)
                    imma16832(acc11[mt][nt], a1[mt], b1[nt >> 1][(nt & 1) * 2], b1[nt >> 1][(nt & 1) * 2 + 1]);
            // P10: a1*b0
#pragma unroll
            for (int mt = 0; mt < 4; mt++)
#pragma unroll
                for (int nt = 0; nt < 4; nt++)
                    imma16832(accX[mt][nt], a1[mt], b0[nt >> 1][(nt & 1) * 2], b0[nt >> 1][(nt & 1) * 2 + 1]);
            // P01: a0*b1
#pragma unroll
            for (int mt = 0; mt < 4; mt++)
#pragma unroll
                for (int nt = 0; nt < 4; nt++)
                    imma16832(accX[mt][nt], a0[mt], b1[nt >> 1][(nt & 1) * 2], b1[nt >> 1][(nt & 1) * 2 + 1]);
        }
    }

    // epilogue: energy = SAB*(P11 + X/256) + c; tanh; dot wv; reduce rows
    const int b = m0 >> 12;
    float cv[8], wvv[8];
#pragma unroll
    for (int nt = 0; nt < 4; nt++)
#pragma unroll
        for (int e = 0; e < 2; e++) {
            int n = n0 + warp_n * 32 + nt * 8 + t * 2 + e;
            cv[nt * 2 + e]  = g_c[b * H + n];
            wvv[nt * 2 + e] = wv[n];
        }
    const float s1 = SAB, s2 = SAB * (1.0f / 256.0f);

#pragma unroll
    for (int mt = 0; mt < 4; mt++) {
        float r0 = 0.0f, r1 = 0.0f;       // rows g and g+8 of this m-tile
#pragma unroll
        for (int nt = 0; nt < 4; nt++) {
            float e0 = s1 * (float)acc11[mt][nt][0] + s2 * (float)accX[mt][nt][0] + cv[nt * 2];
            float e1 = s1 * (float)acc11[mt][nt][1] + s2 * (float)accX[mt][nt][1] + cv[nt * 2 + 1];
            float e2 = s1 * (float)acc11[mt][nt][2] + s2 * (float)accX[mt][nt][2] + cv[nt * 2];
            float e3 = s1 * (float)acc11[mt][nt][3] + s2 * (float)accX[mt][nt][3] + cv[nt * 2 + 1];
            r0 = fmaf(tanhf(e0), wvv[nt * 2],     r0);
            r0 = fmaf(tanhf(e1), wvv[nt * 2 + 1], r0);
            r1 = fmaf(tanhf(e2), wvv[nt * 2],     r1);
            r1 = fmaf(tanhf(e3), wvv[nt * 2 + 1], r1);
        }
        r0 += __shfl_xor_sync(0xffffffffu, r0, 1);
        r0 += __shfl_xor_sync(0xffffffffu, r0, 2);
        r1 += __shfl_xor_sync(0xffffffffu, r1, 1);
        r1 += __shfl_xor_sync(0xffffffffu, r1, 2);
        if (t == 0) {
            atomicAdd(&s_score[warp_m * 64 + mt * 16 + g],     r0);
            atomicAdd(&s_score[warp_m * 64 + mt * 16 + 8 + g], r1);
        }
    }
    __syncthreads();
    if (tid < TILE_M) atomicAdd(&g_scores[m0 + tid], s_score[tid]);
}

// ---------------------------------------------------------------------------
// K_softmax: per-batch softmax over S, in place.
// ---------------------------------------------------------------------------
__global__ void k_softmax() {
    int b = blockIdx.x, tid = threadIdx.x;
    float* sc = g_scores + (size_t)b * SEQ;
    __shared__ float sh[8];
    __shared__ float bc;

    float mx = -3.4e38f;
    for (int i = tid; i < SEQ; i += 256) mx = fmaxf(mx, sc[i]);
#pragma unroll
    for (int o = 16; o > 0; o >>= 1) mx = fmaxf(mx, __shfl_xor_sync(0xffffffffu, mx, o));
    if ((tid & 31) == 0) sh[tid >> 5] = mx;
    __syncthreads();
    if (tid == 0) {
        float m = sh[0];
        for (int i = 1; i < 8; i++) m = fmaxf(m, sh[i]);
        bc = m;
    }
    __syncthreads();
    mx = bc;

    float sum = 0.0f;
    for (int i = tid; i < SEQ; i += 256) {
        float e = expf(sc[i] - mx);
        sc[i] = e;
        sum += e;
    }
#pragma unroll
    for (int o = 16; o > 0; o >>= 1) sum += __shfl_xor_sync(0xffffffffu, sum, o);
    if ((tid & 31) == 0) sh[tid >> 5] = sum;
    __syncthreads();
    if (tid == 0) {
        float s = 0.0f;
        for (int i = 0; i < 8; i++) s += sh[i];
        bc = 1.0f / s;
    }
    __syncthreads();
    float inv = bc;
    for (int i = tid; i < SEQ; i += 256) sc[i] *= inv;
}

// ---------------------------------------------------------------------------
// K_context: context[b,d] = sum_s attn[b,s] * enc[b,s,d]
// ---------------------------------------------------------------------------
__global__ void k_context(const float* __restrict__ enc, float* __restrict__ out) {
    int b = blockIdx.y;
    int s0 = blockIdx.x * 256;
    int col = threadIdx.x * 4;

    const float* attn = g_scores + (size_t)b * SEQ + s0;
    const float* base = enc + ((size_t)b * SEQ + s0) * D2 + col;

    float4 acc = make_float4(0.f, 0.f, 0.f, 0.f);
#pragma unroll 4
    for (int s = 0; s < 256; s++) {
        float a = attn[s];
        float4 e = *(const float4*)(base + (size_t)s * D2);
        acc.x = fmaf(a, e.x, acc.x);
        acc.y = fmaf(a, e.y, acc.y);
        acc.z = fmaf(a, e.z, acc.z);
        acc.w = fmaf(a, e.w, acc.w);
    }
    float* o = out + (size_t)b * D2 + col;
    atomicAdd(&o[0], acc.x);
    atomicAdd(&o[1], acc.y);
    atomicAdd(&o[2], acc.z);
    atomicAdd(&o[3], acc.w);
}

// ---------------------------------------------------------------------------
extern "C" void kernel_launch(void* const* d_in, const int* in_sizes, int n_in,
                              void* d_out, int out_size) {
    const float* hidden = (const float*)d_in[0];  // [16, 1024]
    const float* enc    = (const float*)d_in[1];  // [16, 4096, 1024]
    const float* W      = (const float*)d_in[2];  // [2048, 512]
    const float* bias   = (const float*)d_in[3];  // [512]
    const float* wv     = (const float*)d_in[4];  // [512]
    float* out = (float*)d_out;                   // [16, 1024]

    static bool attr_set = false;
    if (!attr_set) {
        cudaFuncSetAttribute(k_scores, cudaFuncAttributeMaxDynamicSharedMemorySize, SMEM_ALLOC);
        attr_set = true;
    }

    k_init<<<256, 256>>>(out);
    k_precompute<<<BATCH, H>>>(hidden, W, bias);
    k_convB<<<(H * D2) / 256, 256>>>(W);
    k_convA<<<(int)(((size_t)MDIM * D2 / 4) / 256), 256>>>((const float4*)enc);

    dim3 gs(H / TILE_N, MDIM / TILE_M);   // (4, 512)
    k_scores<<<gs, 256, SMEM_ALLOC>>>(wv);

    k_softmax<<<BATCH, 256>>>();

    dim3 gc(SEQ / 256, BATCH);
    k_context<<<gc, 256>>>(enc, out);
}

// round 10
// speedup vs baseline: 2.3259x; 2.3259x over previous
#include <cuda_runtime.h>
#include <cuda_bf16.h>
#include <cstdint>
#include <math.h>

#define BATCH 16
#define SEQ   4096
#define D2    1024
#define H     512
#define MDIM  (BATCH*SEQ)      // 65536

// ---- GEMM tiling ----
#define KT      64             // k-tile (64 elems = 128B bf16 rows)
#define NKT     (D2/KT)        // 16
#define TILE_M  128
#define TILE_N  256

// per-stage smem layout (bytes)
#define AH_OFF 0
#define AL_OFF 16384
#define BH_OFF 32768
#define BL_OFF 65536
#define STAGE_BYTES 98304      // 96 KB
#define SMEM_ALLOC (2*STAGE_BYTES + 256)

// ---------------------------------------------------------------------------
// Device-global scratch (no allocation allowed)
// ---------------------------------------------------------------------------
__device__ __align__(16) __nv_bfloat16 g_Bh[(size_t)H * D2];      // 1MB (W_e^T, [n][k])
__device__ __align__(16) __nv_bfloat16 g_Bl[(size_t)H * D2];      // 1MB
__device__ float g_c[BATCH * H];
__device__ float g_scores[BATCH * SEQ];

// ---------------------------------------------------------------------------
// PTX helpers (baseline ISA only: plain sm_103 target)
// ---------------------------------------------------------------------------
__device__ __forceinline__ uint32_t smem_u32(const void* p) {
    uint32_t a;
    asm("{ .reg .u64 t; cvta.to.shared.u64 t, %1; cvt.u32.u64 %0, t; }" : "=r"(a) : "l"(p));
    return a;
}
__device__ __forceinline__ void cpa16(uint32_t s, const void* g) {
    asm volatile("cp.async.cg.shared.global [%0], [%1], 16;" :: "r"(s), "l"(g) : "memory");
}
__device__ __forceinline__ void sts128(uint32_t addr, uint4 v) {
    asm volatile("st.shared.v4.b32 [%0], {%1,%2,%3,%4};"
        :: "r"(addr), "r"(v.x), "r"(v.y), "r"(v.z), "r"(v.w) : "memory");
}
__device__ __forceinline__ void ldsm4(uint32_t* r, uint32_t addr) {
    asm volatile("ldmatrix.sync.aligned.m8n8.x4.shared.b16 {%0,%1,%2,%3}, [%4];"
        : "=r"(r[0]), "=r"(r[1]), "=r"(r[2]), "=r"(r[3]) : "r"(addr));
}
__device__ __forceinline__ void mma16816(float* d, const uint32_t* a,
                                         uint32_t b0, uint32_t b1) {
    asm volatile(
        "mma.sync.aligned.m16n8k16.row.col.f32.bf16.bf16.f32 "
        "{%0,%1,%2,%3}, {%4,%5,%6,%7}, {%8,%9}, {%0,%1,%2,%3};"
        : "+f"(d[0]), "+f"(d[1]), "+f"(d[2]), "+f"(d[3])
        : "r"(a[0]), "r"(a[1]), "r"(a[2]), "r"(a[3]), "r"(b0), "r"(b1));
}
__device__ __forceinline__ uint32_t swz(uint32_t o) { return o ^ ((o >> 3) & 0x70); }

// 8 floats -> 8 bf16 hi (uint4) + 8 bf16 lo residuals (uint4)
__device__ __forceinline__ void cvt8(float4 u, float4 v, uint4& hi, uint4& lo) {
    float f[8] = {u.x, u.y, u.z, u.w, v.x, v.y, v.z, v.w};
    __nv_bfloat162 hh[4], ll[4];
#pragma unroll
    for (int j = 0; j < 4; j++) {
        __nv_bfloat16 a = __float2bfloat16(f[2*j]);
        __nv_bfloat16 b = __float2bfloat16(f[2*j+1]);
        hh[j] = __halves2bfloat162(a, b);
        ll[j] = __halves2bfloat162(__float2bfloat16(f[2*j]   - __bfloat162float(a)),
                                   __float2bfloat16(f[2*j+1] - __bfloat162float(b)));
    }
    hi = *(uint4*)hh;
    lo = *(uint4*)ll;
}

// ---------------------------------------------------------------------------
// K_init
// ---------------------------------------------------------------------------
__global__ void k_init(float* __restrict__ out) {
    int i = blockIdx.x * blockDim.x + threadIdx.x;
    if (i < BATCH * SEQ) g_scores[i] = 0.0f;
    if (i < BATCH * D2)  out[i] = 0.0f;
}

// ---------------------------------------------------------------------------
// K_precompute: c[b,h] = hidden[b,:] . W_attn[0:D2, h] + b_attn[h]
// ---------------------------------------------------------------------------
__global__ void k_precompute(const float* __restrict__ hidden,
                             const float* __restrict__ W,
                             const float* __restrict__ bias) {
    __shared__ float sh[D2];
    int b = blockIdx.x;
    for (int i = threadIdx.x; i < D2; i += blockDim.x) sh[i] = hidden[(size_t)b * D2 + i];
    __syncthreads();
    int h = threadIdx.x;
    float acc = bias[h];
#pragma unroll 8
    for (int k = 0; k < D2; ++k) acc = fmaf(sh[k], W[(size_t)k * H + h], acc);
    g_c[b * H + h] = acc;
}

// ---------------------------------------------------------------------------
// K_convB: W_e[k][n] -> g_Bh/g_Bl[n][k]  (bf16 hi/lo, transposed to n-major)
// ---------------------------------------------------------------------------
__global__ void k_convB(const float* __restrict__ W) {
    int idx = blockIdx.x * blockDim.x + threadIdx.x;   // H*D2
    int n = idx >> 10, k = idx & 1023;
    float x = W[(size_t)(D2 + k) * H + n];
    __nv_bfloat16 hi = __float2bfloat16(x);
    g_Bh[idx] = hi;
    g_Bl[idx] = __float2bfloat16(x - __bfloat162float(hi));
}

// ---------------------------------------------------------------------------
// K_scores: bf16 3-term GEMM, A converted fp32->bf16 hi/lo in-kernel.
// Grid (2, 512). 256 threads. Warps 2m x 4n, warp tile 64x64.
// ---------------------------------------------------------------------------
__device__ __forceinline__ void load_B(uint32_t stage, int kt, int n0, int tid) {
    const size_t kOff = (size_t)kt * KT;
#pragma unroll
    for (int i = 0; i < 8; ++i) {          // B: 256 rows x 8 16B-chunks = 2048
        int c = tid + 256 * i;
        int row = c >> 3, c16 = c & 7;
        uint32_t so = swz((uint32_t)(row * 128 + c16 * 16));
        size_t e = (size_t)(n0 + row) * D2 + kOff + c16 * 8;
        cpa16(stage + BH_OFF + so, g_Bh + e);
        cpa16(stage + BL_OFF + so, g_Bl + e);
    }
}

__global__ void __launch_bounds__(256, 1)
k_scores(const float* __restrict__ enc, const float* __restrict__ wv) {
    extern __shared__ char smem[];
    uint32_t sb = smem_u32(smem);
    sb = (sb + 127u) & ~127u;

    const int tid = threadIdx.x;
    const int wid = tid >> 5, lane = tid & 31;
    const int warp_m = wid & 1;           // 0..1 -> M offset *64
    const int warp_n = wid >> 1;          // 0..3 -> N offset *64
    const int g = lane >> 2, t = lane & 3;

    const int n0 = blockIdx.x * TILE_N;
    const int m0 = blockIdx.y * TILE_M;

    // A-conversion mapping: thread -> (row, half-row of 32 floats)
    const int a_row  = tid >> 1;          // 0..127
    const int a_half = tid & 1;           // 0..1 (k-offset *32)
    const float* a_base = enc + (size_t)(m0 + a_row) * D2 + a_half * 32;
    const uint32_t a_sbase = (uint32_t)(a_row * 128 + a_half * 64);  // byte offset in tile

    __shared__ float s_score[TILE_M];
    if (tid < TILE_M) s_score[tid] = 0.0f;

    // ldmatrix lane addressing constants
    const int a_lm = ((lane >> 3) & 1) * 8 + (lane & 7);   // m within 16
    const int a_kb = (lane >> 4) * 16;                     // k-byte within 32
    const int b_ln = (lane >> 4) * 8 + (lane & 7);         // n within 16
    const int b_kb = ((lane >> 3) & 1) * 16;

    float d[4][8][4];                     // [mt][nt][frag]  128 accum regs
#pragma unroll
    for (int mt = 0; mt < 4; mt++)
#pragma unroll
        for (int nt = 0; nt < 8; nt++)
#pragma unroll
            for (int e = 0; e < 4; e++) d[mt][nt][e] = 0.0f;

    // ---- prologue: A(0) convert -> stage0; B(0) cp.async -> stage0
    {
#pragma unroll
        for (int c = 0; c < 4; ++c) {
            float4 u = *(const float4*)(a_base + c * 8);
            float4 v = *(const float4*)(a_base + c * 8 + 4);
            uint4 hi, lo;
            cvt8(u, v, hi, lo);
            uint32_t so = swz(a_sbase + c * 16);
            sts128(sb + AH_OFF + so, hi);
            sts128(sb + AL_OFF + so, lo);
        }
    }
    load_B(sb, 0, n0, tid);
    asm volatile("cp.async.commit_group;" ::: "memory");

    for (int kt = 0; kt < NKT; ++kt) {
        const uint32_t cur = sb + (uint32_t)(kt & 1) * STAGE_BYTES;
        const uint32_t nxt = sb + (uint32_t)((kt + 1) & 1) * STAGE_BYTES;
        const bool have_next = (kt + 1 < NKT);

        __syncthreads();   // prev compute done: other stage free for writes

        float4 abuf[8];
        if (have_next) {
            const float* ap = a_base + (size_t)(kt + 1) * KT;
#pragma unroll
            for (int j = 0; j < 8; ++j) abuf[j] = *(const float4*)(ap + j * 4);
            load_B(nxt, kt + 1, n0, tid);
            asm volatile("cp.async.commit_group;" ::: "memory");
            asm volatile("cp.async.wait_group 1;" ::: "memory");
        } else {
            asm volatile("cp.async.wait_group 0;" ::: "memory");
        }
        __syncthreads();   // stage `cur` fully resident (A STS drained, B arrived)

#pragma unroll
        for (int ks = 0; ks < 4; ++ks) {
            uint32_t ah[4][4], bh[4][4], bl[4][4];
            uint32_t a_off[4];
#pragma unroll
            for (int mt = 0; mt < 4; mt++) {
                a_off[mt] = swz((uint32_t)((warp_m * 64 + mt * 16 + a_lm) * 128
                                           + ks * 32 + a_kb));
                ldsm4(ah[mt], cur + AH_OFF + a_off[mt]);
            }
#pragma unroll
            for (int p = 0; p < 4; p++) {
                uint32_t off = swz((uint32_t)((warp_n * 64 + p * 16 + b_ln) * 128
                                              + ks * 32 + b_kb));
                ldsm4(bh[p], cur + BH_OFF + off);
                ldsm4(bl[p], cur + BL_OFF + off);
            }
            // pass 1: Ah * Bh
#pragma unroll
            for (int mt = 0; mt < 4; mt++)
#pragma unroll
                for (int nt = 0; nt < 8; nt++)
                    mma16816(d[mt][nt], ah[mt], bh[nt >> 1][(nt & 1) * 2], bh[nt >> 1][(nt & 1) * 2 + 1]);
            // pass 2: Ah * Bl
#pragma unroll
            for (int mt = 0; mt < 4; mt++)
#pragma unroll
                for (int nt = 0; nt < 8; nt++)
                    mma16816(d[mt][nt], ah[mt], bl[nt >> 1][(nt & 1) * 2], bl[nt >> 1][(nt & 1) * 2 + 1]);
            // reload lo-A into same regs; pass 3: Al * Bh
#pragma unroll
            for (int mt = 0; mt < 4; mt++)
                ldsm4(ah[mt], cur + AL_OFF + a_off[mt]);
#pragma unroll
            for (int mt = 0; mt < 4; mt++)
#pragma unroll
                for (int nt = 0; nt < 8; nt++)
                    mma16816(d[mt][nt], ah[mt], bh[nt >> 1][(nt & 1) * 2], bh[nt >> 1][(nt & 1) * 2 + 1]);

            // deferred A(kt+1) conversion: chunks 0-1 after ks0, 2-3 after ks1
            if (have_next && ks < 2) {
#pragma unroll
                for (int c2 = 0; c2 < 2; ++c2) {
                    int c = ks * 2 + c2;
                    uint4 hi, lo;
                    cvt8(abuf[2 * c], abuf[2 * c + 1], hi, lo);
                    uint32_t so = swz(a_sbase + c * 16);
                    sts128(nxt + AH_OFF + so, hi);
                    sts128(nxt + AL_OFF + so, lo);
                }
            }
        }
    }

    // epilogue: tanh + dot(w_v), reduce to per-row scores
    const int b = m0 >> 12;
    float cv[16], wvv[16];
#pragma unroll
    for (int nt = 0; nt < 8; nt++)
#pragma unroll
        for (int e = 0; e < 2; e++) {
            int n = n0 + warp_n * 64 + nt * 8 + t * 2 + e;
            cv[nt * 2 + e]  = g_c[b * H + n];
            wvv[nt * 2 + e] = wv[n];
        }

#pragma unroll
    for (int mt = 0; mt < 4; mt++) {
        float r0 = 0.0f, r1 = 0.0f;      // rows g and g+8 of this m-tile
#pragma unroll
        for (int nt = 0; nt < 8; nt++) {
            r0 = fmaf(tanhf(d[mt][nt][0] + cv[nt * 2]),     wvv[nt * 2],     r0);
            r0 = fmaf(tanhf(d[mt][nt][1] + cv[nt * 2 + 1]), wvv[nt * 2 + 1], r0);
            r1 = fmaf(tanhf(d[mt][nt][2] + cv[nt * 2]),     wvv[nt * 2],     r1);
            r1 = fmaf(tanhf(d[mt][nt][3] + cv[nt * 2 + 1]), wvv[nt * 2 + 1], r1);
        }
        r0 += __shfl_xor_sync(0xffffffffu, r0, 1);
        r0 += __shfl_xor_sync(0xffffffffu, r0, 2);
        r1 += __shfl_xor_sync(0xffffffffu, r1, 1);
        r1 += __shfl_xor_sync(0xffffffffu, r1, 2);
        if (t == 0) {
            atomicAdd(&s_score[warp_m * 64 + mt * 16 + g],     r0);
            atomicAdd(&s_score[warp_m * 64 + mt * 16 + 8 + g], r1);
        }
    }
    __syncthreads();
    if (tid < TILE_M) atomicAdd(&g_scores[m0 + tid], s_score[tid]);
}

// ---------------------------------------------------------------------------
// K_softmax: per-batch softmax over S, in place.
// ---------------------------------------------------------------------------
__global__ void k_softmax() {
    int b = blockIdx.x, tid = threadIdx.x;
    float* sc = g_scores + (size_t)b * SEQ;
    __shared__ float sh[8];
    __shared__ float bc;

    float mx = -3.4e38f;
    for (int i = tid; i < SEQ; i += 256) mx = fmaxf(mx, sc[i]);
#pragma unroll
    for (int o = 16; o > 0; o >>= 1) mx = fmaxf(mx, __shfl_xor_sync(0xffffffffu, mx, o));
    if ((tid & 31) == 0) sh[tid >> 5] = mx;
    __syncthreads();
    if (tid == 0) {
        float m = sh[0];
        for (int i = 1; i < 8; i++) m = fmaxf(m, sh[i]);
        bc = m;
    }
    __syncthreads();
    mx = bc;

    float sum = 0.0f;
    for (int i = tid; i < SEQ; i += 256) {
        float e = expf(sc[i] - mx);
        sc[i] = e;
        sum += e;
    }
#pragma unroll
    for (int o = 16; o > 0; o >>= 1) sum += __shfl_xor_sync(0xffffffffu, sum, o);
    if ((tid & 31) == 0) sh[tid >> 5] = sum;
    __syncthreads();
    if (tid == 0) {
        float s = 0.0f;
        for (int i = 0; i < 8; i++) s += sh[i];
        bc = 1.0f / s;
    }
    __syncthreads();
    float inv = bc;
    for (int i = tid; i < SEQ; i += 256) sc[i] *= inv;
}

// ---------------------------------------------------------------------------
// K_context: context[b,d] = sum_s attn[b,s] * enc[b,s,d]
// ---------------------------------------------------------------------------
__global__ void k_context(const float* __restrict__ enc, float* __restrict__ out) {
    int b = blockIdx.y;
    int s0 = blockIdx.x * 256;
    int col = threadIdx.x * 4;

    const float* attn = g_scores + (size_t)b * SEQ + s0;
    const float* base = enc + ((size_t)b * SEQ + s0) * D2 + col;

    float4 acc = make_float4(0.f, 0.f, 0.f, 0.f);
#pragma unroll 4
    for (int s = 0; s < 256; s++) {
        float a = attn[s];
        float4 e = *(const float4*)(base + (size_t)s * D2);
        acc.x = fmaf(a, e.x, acc.x);
        acc.y = fmaf(a, e.y, acc.y);
        acc.z = fmaf(a, e.z, acc.z);
        acc.w = fmaf(a, e.w, acc.w);
    }
    float* o = out + (size_t)b * D2 + col;
    atomicAdd(&o[0], acc.x);
    atomicAdd(&o[1], acc.y);
    atomicAdd(&o[2], acc.z);
    atomicAdd(&o[3], acc.w);
}

// ---------------------------------------------------------------------------
extern "C" void kernel_launch(void* const* d_in, const int* in_sizes, int n_in,
                              void* d_out, int out_size) {
    const float* hidden = (const float*)d_in[0];  // [16, 1024]
    const float* enc    = (const float*)d_in[1];  // [16, 4096, 1024]
    const float* W      = (const float*)d_in[2];  // [2048, 512]
    const float* bias   = (const float*)d_in[3];  // [512]
    const float* wv     = (const float*)d_in[4];  // [512]
    float* out = (float*)d_out;                   // [16, 1024]

    static bool attr_set = false;
    if (!attr_set) {
        cudaFuncSetAttribute(k_scores, cudaFuncAttributeMaxDynamicSharedMemorySize, SMEM_ALLOC);
        attr_set = true;
    }

    k_init<<<256, 256>>>(out);
    k_precompute<<<BATCH, H>>>(hidden, W, bias);
    k_convB<<<(H * D2) / 256, 256>>>(W);

    dim3 gs(H / TILE_N, MDIM / TILE_M);   // (2, 512)
    k_scores<<<gs, 256, SMEM_ALLOC>>>(enc, wv);

    k_softmax<<<BATCH, 256>>>();

    dim3 gc(SEQ / 256, BATCH);
    k_context<<<gc, 256>>>(enc, out);
}

// round 15
// speedup vs baseline: 2.3895x; 1.0274x over previous
#include <cuda_runtime.h>
#include <cuda_bf16.h>
#include <cstdint>
#include <math.h>

#define BATCH 16
#define SEQ   4096
#define D2    1024
#define H     512
#define MDIM  (BATCH*SEQ)      // 65536

// ---- GEMM tiling ----
#define KT      64             // k-tile (64 elems = 128B bf16 rows)
#define NKT     (D2/KT)        // 16
#define TILE_M  128
#define TILE_N  256
#define NTHREADS 512

// per-stage smem layout (bytes)
#define AH_OFF 0
#define AL_OFF 16384
#define BH_OFF 32768
#define BL_OFF 65536
#define STAGE_BYTES 98304      // 96 KB
#define SMEM_ALLOC (2*STAGE_BYTES + 256)

// ---------------------------------------------------------------------------
// Device-global scratch (no allocation allowed)
// ---------------------------------------------------------------------------
__device__ __align__(16) __nv_bfloat16 g_Bh[(size_t)H * D2];      // 1MB (W_e^T, [n][k])
__device__ __align__(16) __nv_bfloat16 g_Bl[(size_t)H * D2];      // 1MB
__device__ float g_c[BATCH * H];
__device__ float g_scores[BATCH * SEQ];

// ---------------------------------------------------------------------------
// PTX helpers (baseline ISA only: plain sm_103 target)
// ---------------------------------------------------------------------------
__device__ __forceinline__ uint32_t smem_u32(const void* p) {
    uint32_t a;
    asm("{ .reg .u64 t; cvta.to.shared.u64 t, %1; cvt.u32.u64 %0, t; }" : "=r"(a) : "l"(p));
    return a;
}
__device__ __forceinline__ void cpa16(uint32_t s, const void* g) {
    asm volatile("cp.async.cg.shared.global [%0], [%1], 16;" :: "r"(s), "l"(g) : "memory");
}
__device__ __forceinline__ void sts128(uint32_t addr, uint4 v) {
    asm volatile("st.shared.v4.b32 [%0], {%1,%2,%3,%4};"
        :: "r"(addr), "r"(v.x), "r"(v.y), "r"(v.z), "r"(v.w) : "memory");
}
__device__ __forceinline__ void ldsm4(uint32_t* r, uint32_t addr) {
    asm volatile("ldmatrix.sync.aligned.m8n8.x4.shared.b16 {%0,%1,%2,%3}, [%4];"
        : "=r"(r[0]), "=r"(r[1]), "=r"(r[2]), "=r"(r[3]) : "r"(addr));
}
__device__ __forceinline__ void mma16816(float* d, const uint32_t* a,
                                         uint32_t b0, uint32_t b1) {
    asm volatile(
        "mma.sync.aligned.m16n8k16.row.col.f32.bf16.bf16.f32 "
        "{%0,%1,%2,%3}, {%4,%5,%6,%7}, {%8,%9}, {%0,%1,%2,%3};"
        : "+f"(d[0]), "+f"(d[1]), "+f"(d[2]), "+f"(d[3])
        : "r"(a[0]), "r"(a[1]), "r"(a[2]), "r"(a[3]), "r"(b0), "r"(b1));
}
__device__ __forceinline__ uint32_t swz(uint32_t o) { return o ^ ((o >> 3) & 0x70); }

// 8 floats -> 8 bf16 hi (uint4) + 8 bf16 lo residuals (uint4)
__device__ __forceinline__ void cvt8(float4 u, float4 v, uint4& hi, uint4& lo) {
    float f[8] = {u.x, u.y, u.z, u.w, v.x, v.y, v.z, v.w};
    __nv_bfloat162 hh[4], ll[4];
#pragma unroll
    for (int j = 0; j < 4; j++) {
        __nv_bfloat16 a = __float2bfloat16(f[2*j]);
        __nv_bfloat16 b = __float2bfloat16(f[2*j+1]);
        hh[j] = __halves2bfloat162(a, b);
        ll[j] = __halves2bfloat162(__float2bfloat16(f[2*j]   - __bfloat162float(a)),
                                   __float2bfloat16(f[2*j+1] - __bfloat162float(b)));
    }
    hi = *(uint4*)hh;
    lo = *(uint4*)ll;
}

// ---------------------------------------------------------------------------
// K_init
// ---------------------------------------------------------------------------
__global__ void k_init(float* __restrict__ out) {
    int i = blockIdx.x * blockDim.x + threadIdx.x;
    if (i < BATCH * SEQ) g_scores[i] = 0.0f;
    if (i < BATCH * D2)  out[i] = 0.0f;
}

// ---------------------------------------------------------------------------
// K_precompute: c[b,h] = hidden[b,:] . W_attn[0:D2, h] + b_attn[h]
// ---------------------------------------------------------------------------
__global__ void k_precompute(const float* __restrict__ hidden,
                             const float* __restrict__ W,
                             const float* __restrict__ bias) {
    __shared__ float sh[D2];
    int b = blockIdx.x;
    for (int i = threadIdx.x; i < D2; i += blockDim.x) sh[i] = hidden[(size_t)b * D2 + i];
    __syncthreads();
    int h = threadIdx.x;
    float acc = bias[h];
#pragma unroll 8
    for (int k = 0; k < D2; ++k) acc = fmaf(sh[k], W[(size_t)k * H + h], acc);
    g_c[b * H + h] = acc;
}

// ---------------------------------------------------------------------------
// K_convB: W_e[k][n] -> g_Bh/g_Bl[n][k]  (bf16 hi/lo, transposed to n-major)
// ---------------------------------------------------------------------------
__global__ void k_convB(const float* __restrict__ W) {
    int idx = blockIdx.x * blockDim.x + threadIdx.x;   // H*D2
    int n = idx >> 10, k = idx & 1023;
    float x = W[(size_t)(D2 + k) * H + n];
    __nv_bfloat16 hi = __float2bfloat16(x);
    g_Bh[idx] = hi;
    g_Bl[idx] = __float2bfloat16(x - __bfloat162float(hi));
}

// ---------------------------------------------------------------------------
// K_scores: bf16 3-term GEMM, A converted fp32->bf16 hi/lo in-kernel.
// Grid (2, 512). 512 threads, 16 warps (2m x 8n), warp tile 64x32.
// ---------------------------------------------------------------------------
__device__ __forceinline__ void load_B(uint32_t stage, int kt, int n0, int tid) {
    const size_t kOff = (size_t)kt * KT;
#pragma unroll
    for (int i = 0; i < 4; ++i) {          // B: 256 rows x 8 16B-chunks = 2048
        int c = tid + NTHREADS * i;
        int row = c >> 3, c16 = c & 7;
        uint32_t so = swz((uint32_t)(row * 128 + c16 * 16));
        size_t e = (size_t)(n0 + row) * D2 + kOff + c16 * 8;
        cpa16(stage + BH_OFF + so, g_Bh + e);
        cpa16(stage + BL_OFF + so, g_Bl + e);
    }
}

__global__ void __launch_bounds__(NTHREADS, 1)
k_scores(const float* __restrict__ enc, const float* __restrict__ wv) {
    extern __shared__ char smem[];
    uint32_t sb = smem_u32(smem);
    sb = (sb + 127u) & ~127u;

    const int tid = threadIdx.x;
    const int wid = tid >> 5, lane = tid & 31;
    const int warp_m = wid & 1;           // 0..1 -> M offset *64
    const int warp_n = wid >> 1;          // 0..7 -> N offset *32
    const int g = lane >> 2, t = lane & 3;

    const int n0 = blockIdx.x * TILE_N;
    const int m0 = blockIdx.y * TILE_M;

    // A-conversion mapping: thread -> (row, quarter of 16 floats)
    const int a_row = tid >> 2;           // 0..127
    const int a_q   = tid & 3;            // 0..3 (16 floats each)
    const float* a_base = enc + (size_t)(m0 + a_row) * D2 + a_q * 16;
    const uint32_t a_sbase = (uint32_t)(a_row * 128 + a_q * 32);  // byte offset in tile

    __shared__ float s_score[TILE_M];
    if (tid < TILE_M) s_score[tid] = 0.0f;

    // ldmatrix lane addressing constants
    const int a_lm = ((lane >> 3) & 1) * 8 + (lane & 7);   // m within 16
    const int a_kb = (lane >> 4) * 16;                     // k-byte within 32
    const int b_ln = (lane >> 4) * 8 + (lane & 7);         // n within 16
    const int b_kb = ((lane >> 3) & 1) * 16;

    float d[4][4][4];                     // [mt][nt][frag]  64 accum regs
#pragma unroll
    for (int mt = 0; mt < 4; mt++)
#pragma unroll
        for (int nt = 0; nt < 4; nt++)
#pragma unroll
            for (int e = 0; e < 4; e++) d[mt][nt][e] = 0.0f;

    // ---- prologue: A(0) convert -> stage0; B(0) cp.async -> stage0
    {
#pragma unroll
        for (int c = 0; c < 2; ++c) {
            float4 u = *(const float4*)(a_base + c * 8);
            float4 v = *(const float4*)(a_base + c * 8 + 4);
            uint4 hi, lo;
            cvt8(u, v, hi, lo);
            uint32_t so = swz(a_sbase + c * 16);
            sts128(sb + AH_OFF + so, hi);
            sts128(sb + AL_OFF + so, lo);
        }
    }
    load_B(sb, 0, n0, tid);
    asm volatile("cp.async.commit_group;" ::: "memory");

    for (int kt = 0; kt < NKT; ++kt) {
        const uint32_t cur = sb + (uint32_t)(kt & 1) * STAGE_BYTES;
        const uint32_t nxt = sb + (uint32_t)((kt + 1) & 1) * STAGE_BYTES;
        const bool have_next = (kt + 1 < NKT);

        __syncthreads();   // prev compute done: other stage free for writes

        if (have_next) {
            load_B(nxt, kt + 1, n0, tid);
            asm volatile("cp.async.commit_group;" ::: "memory");
            asm volatile("cp.async.wait_group 1;" ::: "memory");
        } else {
            asm volatile("cp.async.wait_group 0;" ::: "memory");
        }
        __syncthreads();   // stage `cur` fully resident (A STS drained, B arrived)

        float4 abuf[4];    // transient: spans one ks iteration only
#pragma unroll
        for (int ks = 0; ks < 4; ++ks) {
            // A(kt+1) conversion interleave:
            //   ks0 / ks1 : issue LDG of 2 float4 pairs
            //   ks1 / ks2 : convert + STS into next stage
            if (have_next && (ks == 0 || ks == 1)) {
                const float* ap = a_base + (size_t)(kt + 1) * KT + ks * 8;
                abuf[ks * 2]     = *(const float4*)(ap);
                abuf[ks * 2 + 1] = *(const float4*)(ap + 4);
            }

            uint32_t ah[4][4], bh[2][4], bl[2][4];
            uint32_t a_off[4];
#pragma unroll
            for (int mt = 0; mt < 4; mt++) {
                a_off[mt] = swz((uint32_t)((warp_m * 64 + mt * 16 + a_lm) * 128
                                           + ks * 32 + a_kb));
                ldsm4(ah[mt], cur + AH_OFF + a_off[mt]);
            }
#pragma unroll
            for (int p = 0; p < 2; p++) {
                uint32_t off = swz((uint32_t)((warp_n * 32 + p * 16 + b_ln) * 128
                                              + ks * 32 + b_kb));
                ldsm4(bh[p], cur + BH_OFF + off);
                ldsm4(bl[p], cur + BL_OFF + off);
            }
            // pass 1: Ah * Bh
#pragma unroll
            for (int mt = 0; mt < 4; mt++)
#pragma unroll
                for (int nt = 0; nt < 4; nt++)
                    mma16816(d[mt][nt], ah[mt], bh[nt >> 1][(nt & 1) * 2], bh[nt >> 1][(nt & 1) * 2 + 1]);
            // pass 2: Ah * Bl
#pragma unroll
            for (int mt = 0; mt < 4; mt++)
#pragma unroll
                for (int nt = 0; nt < 4; nt++)
                    mma16816(d[mt][nt], ah[mt], bl[nt >> 1][(nt & 1) * 2], bl[nt >> 1][(nt & 1) * 2 + 1]);
            // reload lo-A into same regs; pass 3: Al * Bh
#pragma unroll
            for (int mt = 0; mt < 4; mt++)
                ldsm4(ah[mt], cur + AL_OFF + a_off[mt]);
#pragma unroll
            for (int mt = 0; mt < 4; mt++)
#pragma unroll
                for (int nt = 0; nt < 4; nt++)
                    mma16816(d[mt][nt], ah[mt], bh[nt >> 1][(nt & 1) * 2], bh[nt >> 1][(nt & 1) * 2 + 1]);

            if (have_next && (ks == 1 || ks == 2)) {
                int c = ks - 1;                     // chunk 0 at ks1, chunk 1 at ks2
                uint4 hi, lo;
                cvt8(abuf[c * 2], abuf[c * 2 + 1], hi, lo);
                uint32_t so = swz(a_sbase + c * 16);
                sts128(nxt + AH_OFF + so, hi);
                sts128(nxt + AL_OFF + so, lo);
            }
        }
    }

    // epilogue: tanh + dot(w_v), reduce to per-row scores
    const int b = m0 >> 12;
    float cv[8], wvv[8];
#pragma unroll
    for (int nt = 0; nt < 4; nt++)
#pragma unroll
        for (int e = 0; e < 2; e++) {
            int n = n0 + warp_n * 32 + nt * 8 + t * 2 + e;
            cv[nt * 2 + e]  = g_c[b * H + n];
            wvv[nt * 2 + e] = wv[n];
        }

#pragma unroll
    for (int mt = 0; mt < 4; mt++) {
        float r0 = 0.0f, r1 = 0.0f;      // rows g and g+8 of this m-tile
#pragma unroll
        for (int nt = 0; nt < 4; nt++) {
            r0 = fmaf(tanhf(d[mt][nt][0] + cv[nt * 2]),     wvv[nt * 2],     r0);
            r0 = fmaf(tanhf(d[mt][nt][1] + cv[nt * 2 + 1]), wvv[nt * 2 + 1], r0);
            r1 = fmaf(tanhf(d[mt][nt][2] + cv[nt * 2]),     wvv[nt * 2],     r1);
            r1 = fmaf(tanhf(d[mt][nt][3] + cv[nt * 2 + 1]), wvv[nt * 2 + 1], r1);
        }
        r0 += __shfl_xor_sync(0xffffffffu, r0, 1);
        r0 += __shfl_xor_sync(0xffffffffu, r0, 2);
        r1 += __shfl_xor_sync(0xffffffffu, r1, 1);
        r1 += __shfl_xor_sync(0xffffffffu, r1, 2);
        if (t == 0) {
            atomicAdd(&s_score[warp_m * 64 + mt * 16 + g],     r0);
            atomicAdd(&s_score[warp_m * 64 + mt * 16 + 8 + g], r1);
        }
    }
    __syncthreads();
    if (tid < TILE_M) atomicAdd(&g_scores[m0 + tid], s_score[tid]);
}

// ---------------------------------------------------------------------------
// K_softmax: per-batch softmax over S, in place.
// ---------------------------------------------------------------------------
__global__ void k_softmax() {
    int b = blockIdx.x, tid = threadIdx.x;
    float* sc = g_scores + (size_t)b * SEQ;
    __shared__ float sh[8];
    __shared__ float bc;

    float mx = -3.4e38f;
    for (int i = tid; i < SEQ; i += 256) mx = fmaxf(mx, sc[i]);
#pragma unroll
    for (int o = 16; o > 0; o >>= 1) mx = fmaxf(mx, __shfl_xor_sync(0xffffffffu, mx, o));
    if ((tid & 31) == 0) sh[tid >> 5] = mx;
    __syncthreads();
    if (tid == 0) {
        float m = sh[0];
        for (int i = 1; i < 8; i++) m = fmaxf(m, sh[i]);
        bc = m;
    }
    __syncthreads();
    mx = bc;

    float sum = 0.0f;
    for (int i = tid; i < SEQ; i += 256) {
        float e = expf(sc[i] - mx);
        sc[i] = e;
        sum += e;
    }
#pragma unroll
    for (int o = 16; o > 0; o >>= 1) sum += __shfl_xor_sync(0xffffffffu, sum, o);
    if ((tid & 31) == 0) sh[tid >> 5] = sum;
    __syncthreads();
    if (tid == 0) {
        float s = 0.0f;
        for (int i = 0; i < 8; i++) s += sh[i];
        bc = 1.0f / s;
    }
    __syncthreads();
    float inv = bc;
    for (int i = tid; i < SEQ; i += 256) sc[i] *= inv;
}

// ---------------------------------------------------------------------------
// K_context: context[b,d] = sum_s attn[b,s] * enc[b,s,d]
// ---------------------------------------------------------------------------
__global__ void k_context(const float* __restrict__ enc, float* __restrict__ out) {
    int b = blockIdx.y;
    int s0 = blockIdx.x * 256;
    int col = threadIdx.x * 4;

    const float* attn = g_scores + (size_t)b * SEQ + s0;
    const float* base = enc + ((size_t)b * SEQ + s0) * D2 + col;

    float4 acc = make_float4(0.f, 0.f, 0.f, 0.f);
#pragma unroll 4
    for (int s = 0; s < 256; s++) {
        float a = attn[s];
        float4 e = *(const float4*)(base + (size_t)s * D2);
        acc.x = fmaf(a, e.x, acc.x);
        acc.y = fmaf(a, e.y, acc.y);
        acc.z = fmaf(a, e.z, acc.z);
        acc.w = fmaf(a, e.w, acc.w);
    }
    float* o = out + (size_t)b * D2 + col;
    atomicAdd(&o[0], acc.x);
    atomicAdd(&o[1], acc.y);
    atomicAdd(&o[2], acc.z);
    atomicAdd(&o[3], acc.w);
}

// ---------------------------------------------------------------------------
extern "C" void kernel_launch(void* const* d_in, const int* in_sizes, int n_in,
                              void* d_out, int out_size) {
    const float* hidden = (const float*)d_in[0];  // [16, 1024]
    const float* enc    = (const float*)d_in[1];  // [16, 4096, 1024]
    const float* W      = (const float*)d_in[2];  // [2048, 512]
    const float* bias   = (const float*)d_in[3];  // [512]
    const float* wv     = (const float*)d_in[4];  // [512]
    float* out = (float*)d_out;                   // [16, 1024]

    static bool attr_set = false;
    if (!attr_set) {
        cudaFuncSetAttribute(k_scores, cudaFuncAttributeMaxDynamicSharedMemorySize, SMEM_ALLOC);
        attr_set = true;
    }

    k_init<<<256, 256>>>(out);
    k_precompute<<<BATCH, H>>>(hidden, W, bias);
    k_convB<<<(H * D2) / 256, 256>>>(W);

    dim3 gs(H / TILE_N, MDIM / TILE_M);   // (2, 512)
    k_scores<<<gs, NTHREADS, SMEM_ALLOC>>>(enc, wv);

    k_softmax<<<BATCH, 256>>>();

    dim3 gc(SEQ / 256, BATCH);
    k_context<<<gc, 256>>>(enc, out);
}

// round 16
// speedup vs baseline: 2.9682x; 1.2422x over previous
#include <cuda_runtime.h>
#include <cuda_bf16.h>
#include <cuda_fp16.h>
#include <cstdint>
#include <math.h>

#define BATCH 16
#define SEQ   4096
#define D2    1024
#define H     512
#define MDIM  (BATCH*SEQ)      // 65536

// ---- GEMM tiling ----
#define KT      64             // k-tile (64 elems = 128B fp16 rows)
#define NKT     (D2/KT)        // 16
#define TILE_M  128
#define TILE_N  256
#define NTHREADS 512

// per-stage smem layout (bytes): A (fp16 single) 16KB, Bh 32KB, Bl 32KB
#define A_OFF  0
#define BH_OFF 16384
#define BL_OFF 49152
#define STAGE_BYTES 81920      // 80 KB
#define SMEM_ALLOC (2*STAGE_BYTES + 256)

// ---------------------------------------------------------------------------
// Device-global scratch (no allocation allowed)
// ---------------------------------------------------------------------------
__device__ __align__(16) __half g_Bh[(size_t)H * D2];   // 1MB (W_e^T hi, [n][k])
__device__ __align__(16) __half g_Bl[(size_t)H * D2];   // 1MB (W_e^T residual)
__device__ float g_c[BATCH * H];
__device__ float g_scores[BATCH * SEQ];

// ---------------------------------------------------------------------------
// PTX helpers (baseline ISA only: plain sm_103 target)
// ---------------------------------------------------------------------------
__device__ __forceinline__ uint32_t smem_u32(const void* p) {
    uint32_t a;
    asm("{ .reg .u64 t; cvta.to.shared.u64 t, %1; cvt.u32.u64 %0, t; }" : "=r"(a) : "l"(p));
    return a;
}
__device__ __forceinline__ void cpa16(uint32_t s, const void* g) {
    asm volatile("cp.async.cg.shared.global [%0], [%1], 16;" :: "r"(s), "l"(g) : "memory");
}
__device__ __forceinline__ void sts128(uint32_t addr, uint4 v) {
    asm volatile("st.shared.v4.b32 [%0], {%1,%2,%3,%4};"
        :: "r"(addr), "r"(v.x), "r"(v.y), "r"(v.z), "r"(v.w) : "memory");
}
__device__ __forceinline__ void ldsm4(uint32_t* r, uint32_t addr) {
    asm volatile("ldmatrix.sync.aligned.m8n8.x4.shared.b16 {%0,%1,%2,%3}, [%4];"
        : "=r"(r[0]), "=r"(r[1]), "=r"(r[2]), "=r"(r[3]) : "r"(addr));
}
__device__ __forceinline__ void mma16816(float* d, const uint32_t* a,
                                         uint32_t b0, uint32_t b1) {
    asm volatile(
        "mma.sync.aligned.m16n8k16.row.col.f32.f16.f16.f32 "
        "{%0,%1,%2,%3}, {%4,%5,%6,%7}, {%8,%9}, {%0,%1,%2,%3};"
        : "+f"(d[0]), "+f"(d[1]), "+f"(d[2]), "+f"(d[3])
        : "r"(a[0]), "r"(a[1]), "r"(a[2]), "r"(a[3]), "r"(b0), "r"(b1));
}
__device__ __forceinline__ uint32_t swz(uint32_t o) { return o ^ ((o >> 3) & 0x70); }

// 8 floats -> 8 fp16 packed in a uint4
__device__ __forceinline__ uint4 cvt8h(float4 u, float4 v) {
    __half2 hh[4];
    hh[0] = __floats2half2_rn(u.x, u.y);
    hh[1] = __floats2half2_rn(u.z, u.w);
    hh[2] = __floats2half2_rn(v.x, v.y);
    hh[3] = __floats2half2_rn(v.z, v.w);
    return *(uint4*)hh;
}

// ---------------------------------------------------------------------------
// K_init
// ---------------------------------------------------------------------------
__global__ void k_init(float* __restrict__ out) {
    int i = blockIdx.x * blockDim.x + threadIdx.x;
    if (i < BATCH * SEQ) g_scores[i] = 0.0f;
    if (i < BATCH * D2)  out[i] = 0.0f;
}

// ---------------------------------------------------------------------------
// K_precompute: c[b,h] = hidden[b,:] . W_attn[0:D2, h] + b_attn[h]  (exact fp32)
// ---------------------------------------------------------------------------
__global__ void k_precompute(const float* __restrict__ hidden,
                             const float* __restrict__ W,
                             const float* __restrict__ bias) {
    __shared__ float sh[D2];
    int b = blockIdx.x;
    for (int i = threadIdx.x; i < D2; i += blockDim.x) sh[i] = hidden[(size_t)b * D2 + i];
    __syncthreads();
    int h = threadIdx.x;
    float acc = bias[h];
#pragma unroll 8
    for (int k = 0; k < D2; ++k) acc = fmaf(sh[k], W[(size_t)k * H + h], acc);
    g_c[b * H + h] = acc;
}

// ---------------------------------------------------------------------------
// K_convB: W_e[k][n] -> g_Bh/g_Bl[n][k]  (fp16 hi + exact residual, n-major)
// ---------------------------------------------------------------------------
__global__ void k_convB(const float* __restrict__ W) {
    int idx = blockIdx.x * blockDim.x + threadIdx.x;   // H*D2
    int n = idx >> 10, k = idx & 1023;
    float x = W[(size_t)(D2 + k) * H + n];
    __half hi = __float2half(x);
    g_Bh[idx] = hi;
    g_Bl[idx] = __float2half(x - __half2float(hi));
}

// ---------------------------------------------------------------------------
// K_scores: 2-pass fp16 GEMM (A single-rounded, B hi/lo split), A converted
// fp32->fp16 in-kernel. Grid (2, 512). 512 threads, warps 2m x 8n, tile 64x32.
// ---------------------------------------------------------------------------
__device__ __forceinline__ void load_B(uint32_t stage, int kt, int n0, int tid) {
    const size_t kOff = (size_t)kt * KT;
#pragma unroll
    for (int i = 0; i < 4; ++i) {          // B: 256 rows x 8 16B-chunks = 2048
        int c = tid + NTHREADS * i;
        int row = c >> 3, c16 = c & 7;
        uint32_t so = swz((uint32_t)(row * 128 + c16 * 16));
        size_t e = (size_t)(n0 + row) * D2 + kOff + c16 * 8;
        cpa16(stage + BH_OFF + so, g_Bh + e);
        cpa16(stage + BL_OFF + so, g_Bl + e);
    }
}

__global__ void __launch_bounds__(NTHREADS, 1)
k_scores(const float* __restrict__ enc, const float* __restrict__ wv) {
    extern __shared__ char smem[];
    uint32_t sb = smem_u32(smem);
    sb = (sb + 127u) & ~127u;

    const int tid = threadIdx.x;
    const int wid = tid >> 5, lane = tid & 31;
    const int warp_m = wid & 1;           // 0..1 -> M offset *64
    const int warp_n = wid >> 1;          // 0..7 -> N offset *32
    const int g = lane >> 2, t = lane & 3;

    const int n0 = blockIdx.x * TILE_N;
    const int m0 = blockIdx.y * TILE_M;

    // A-conversion mapping: thread -> (row, quarter of 16 floats)
    const int a_row = tid >> 2;           // 0..127
    const int a_q   = tid & 3;            // 0..3 (16 floats each)
    const float* a_base = enc + (size_t)(m0 + a_row) * D2 + a_q * 16;
    const uint32_t a_sbase = (uint32_t)(a_row * 128 + a_q * 32);  // byte offset in tile

    __shared__ float s_score[TILE_M];
    if (tid < TILE_M) s_score[tid] = 0.0f;

    // ldmatrix lane addressing constants
    const int a_lm = ((lane >> 3) & 1) * 8 + (lane & 7);   // m within 16
    const int a_kb = (lane >> 4) * 16;                     // k-byte within 32
    const int b_ln = (lane >> 4) * 8 + (lane & 7);         // n within 16
    const int b_kb = ((lane >> 3) & 1) * 16;

    float d[4][4][4];                     // [mt][nt][frag]  64 accum regs
#pragma unroll
    for (int mt = 0; mt < 4; mt++)
#pragma unroll
        for (int nt = 0; nt < 4; nt++)
#pragma unroll
            for (int e = 0; e < 4; e++) d[mt][nt][e] = 0.0f;

    // ---- prologue: A(0) convert -> stage0; B(0) cp.async -> stage0
#pragma unroll
    for (int c = 0; c < 2; ++c) {
        float4 u = *(const float4*)(a_base + c * 8);
        float4 v = *(const float4*)(a_base + c * 8 + 4);
        sts128(sb + A_OFF + swz(a_sbase + c * 16), cvt8h(u, v));
    }
    load_B(sb, 0, n0, tid);
    asm volatile("cp.async.commit_group;" ::: "memory");

    for (int kt = 0; kt < NKT; ++kt) {
        const uint32_t cur = sb + (uint32_t)(kt & 1) * STAGE_BYTES;
        const uint32_t nxt = sb + (uint32_t)((kt + 1) & 1) * STAGE_BYTES;
        const bool have_next = (kt + 1 < NKT);

        __syncthreads();   // prev compute done: other stage free for writes

        if (have_next) {
            load_B(nxt, kt + 1, n0, tid);
            asm volatile("cp.async.commit_group;" ::: "memory");
            asm volatile("cp.async.wait_group 1;" ::: "memory");
        } else {
            asm volatile("cp.async.wait_group 0;" ::: "memory");
        }
        __syncthreads();   // stage `cur` fully resident (A STS drained, B arrived)

        float4 abuf[4];    // transient A prefetch (spans <=2 ks)
#pragma unroll
        for (int ks = 0; ks < 4; ++ks) {
            // A(kt+1): LDG chunk0 at ks0, chunk1 at ks1; cvt+STS at ks1/ks2
            if (have_next && (ks == 0 || ks == 1)) {
                const float* ap = a_base + (size_t)(kt + 1) * KT + ks * 8;
                abuf[ks * 2]     = *(const float4*)(ap);
                abuf[ks * 2 + 1] = *(const float4*)(ap + 4);
            }

            uint32_t ah[4][4], bh[2][4], bl[2][4];
#pragma unroll
            for (int mt = 0; mt < 4; mt++) {
                uint32_t off = swz((uint32_t)((warp_m * 64 + mt * 16 + a_lm) * 128
                                              + ks * 32 + a_kb));
                ldsm4(ah[mt], cur + A_OFF + off);
            }
#pragma unroll
            for (int p = 0; p < 2; p++) {
                uint32_t off = swz((uint32_t)((warp_n * 32 + p * 16 + b_ln) * 128
                                              + ks * 32 + b_kb));
                ldsm4(bh[p], cur + BH_OFF + off);
                ldsm4(bl[p], cur + BL_OFF + off);
            }
            // pass 1: A * Bh
#pragma unroll
            for (int mt = 0; mt < 4; mt++)
#pragma unroll
                for (int nt = 0; nt < 4; nt++)
                    mma16816(d[mt][nt], ah[mt], bh[nt >> 1][(nt & 1) * 2], bh[nt >> 1][(nt & 1) * 2 + 1]);
            // pass 2: A * Bl  (A fragments stay resident)
#pragma unroll
            for (int mt = 0; mt < 4; mt++)
#pragma unroll
                for (int nt = 0; nt < 4; nt++)
                    mma16816(d[mt][nt], ah[mt], bl[nt >> 1][(nt & 1) * 2], bl[nt >> 1][(nt & 1) * 2 + 1]);

            if (have_next && (ks == 1 || ks == 2)) {
                int c = ks - 1;                 // chunk 0 at ks1, chunk 1 at ks2
                uint4 hv = cvt8h(abuf[c * 2], abuf[c * 2 + 1]);
                sts128(nxt + A_OFF + swz(a_sbase + c * 16), hv);
            }
        }
    }

    // epilogue: tanh + dot(w_v), reduce to per-row scores
    const int b = m0 >> 12;
    float cv[8], wvv[8];
#pragma unroll
    for (int nt = 0; nt < 4; nt++)
#pragma unroll
        for (int e = 0; e < 2; e++) {
            int n = n0 + warp_n * 32 + nt * 8 + t * 2 + e;
            cv[nt * 2 + e]  = g_c[b * H + n];
            wvv[nt * 2 + e] = wv[n];
        }

#pragma unroll
    for (int mt = 0; mt < 4; mt++) {
        float r0 = 0.0f, r1 = 0.0f;      // rows g and g+8 of this m-tile
#pragma unroll
        for (int nt = 0; nt < 4; nt++) {
            r0 = fmaf(tanhf(d[mt][nt][0] + cv[nt * 2]),     wvv[nt * 2],     r0);
            r0 = fmaf(tanhf(d[mt][nt][1] + cv[nt * 2 + 1]), wvv[nt * 2 + 1], r0);
            r1 = fmaf(tanhf(d[mt][nt][2] + cv[nt * 2]),     wvv[nt * 2],     r1);
            r1 = fmaf(tanhf(d[mt][nt][3] + cv[nt * 2 + 1]), wvv[nt * 2 + 1], r1);
        }
        r0 += __shfl_xor_sync(0xffffffffu, r0, 1);
        r0 += __shfl_xor_sync(0xffffffffu, r0, 2);
        r1 += __shfl_xor_sync(0xffffffffu, r1, 1);
        r1 += __shfl_xor_sync(0xffffffffu, r1, 2);
        if (t == 0) {
            atomicAdd(&s_score[warp_m * 64 + mt * 16 + g],     r0);
            atomicAdd(&s_score[warp_m * 64 + mt * 16 + 8 + g], r1);
        }
    }
    __syncthreads();
    if (tid < TILE_M) atomicAdd(&g_scores[m0 + tid], s_score[tid]);
}

// ---------------------------------------------------------------------------
// K_softmax: per-batch softmax over S, in place.
// ---------------------------------------------------------------------------
__global__ void k_softmax() {
    int b = blockIdx.x, tid = threadIdx.x;
    float* sc = g_scores + (size_t)b * SEQ;
    __shared__ float sh[8];
    __shared__ float bc;

    float mx = -3.4e38f;
    for (int i = tid; i < SEQ; i += 256) mx = fmaxf(mx, sc[i]);
#pragma unroll
    for (int o = 16; o > 0; o >>= 1) mx = fmaxf(mx, __shfl_xor_sync(0xffffffffu, mx, o));
    if ((tid & 31) == 0) sh[tid >> 5] = mx;
    __syncthreads();
    if (tid == 0) {
        float m = sh[0];
        for (int i = 1; i < 8; i++) m = fmaxf(m, sh[i]);
        bc = m;
    }
    __syncthreads();
    mx = bc;

    float sum = 0.0f;
    for (int i = tid; i < SEQ; i += 256) {
        float e = expf(sc[i] - mx);
        sc[i] = e;
        sum += e;
    }
#pragma unroll
    for (int o = 16; o > 0; o >>= 1) sum += __shfl_xor_sync(0xffffffffu, sum, o);
    if ((tid & 31) == 0) sh[tid >> 5] = sum;
    __syncthreads();
    if (tid == 0) {
        float s = 0.0f;
        for (int i = 0; i < 8; i++) s += sh[i];
        bc = 1.0f / s;
    }
    __syncthreads();
    float inv = bc;
    for (int i = tid; i < SEQ; i += 256) sc[i] *= inv;
}

// ---------------------------------------------------------------------------
// K_context: context[b,d] = sum_s attn[b,s] * enc[b,s,d]
// ---------------------------------------------------------------------------
__global__ void k_context(const float* __restrict__ enc, float* __restrict__ out) {
    int b = blockIdx.y;
    int s0 = blockIdx.x * 256;
    int col = threadIdx.x * 4;

    const float* attn = g_scores + (size_t)b * SEQ + s0;
    const float* base = enc + ((size_t)b * SEQ + s0) * D2 + col;

    float4 acc = make_float4(0.f, 0.f, 0.f, 0.f);
#pragma unroll 4
    for (int s = 0; s < 256; s++) {
        float a = attn[s];
        float4 e = *(const float4*)(base + (size_t)s * D2);
        acc.x = fmaf(a, e.x, acc.x);
        acc.y = fmaf(a, e.y, acc.y);
        acc.z = fmaf(a, e.z, acc.z);
        acc.w = fmaf(a, e.w, acc.w);
    }
    float* o = out + (size_t)b * D2 + col;
    atomicAdd(&o[0], acc.x);
    atomicAdd(&o[1], acc.y);
    atomicAdd(&o[2], acc.z);
    atomicAdd(&o[3], acc.w);
}

// ---------------------------------------------------------------------------
extern "C" void kernel_launch(void* const* d_in, const int* in_sizes, int n_in,
                              void* d_out, int out_size) {
    const float* hidden = (const float*)d_in[0];  // [16, 1024]
    const float* enc    = (const float*)d_in[1];  // [16, 4096, 1024]
    const float* W      = (const float*)d_in[2];  // [2048, 512]
    const float* bias   = (const float*)d_in[3];  // [512]
    const float* wv     = (const float*)d_in[4];  // [512]
    float* out = (float*)d_out;                   // [16, 1024]

    static bool attr_set = false;
    if (!attr_set) {
        cudaFuncSetAttribute(k_scores, cudaFuncAttributeMaxDynamicSharedMemorySize, SMEM_ALLOC);
        attr_set = true;
    }

    k_init<<<256, 256>>>(out);
    k_precompute<<<BATCH, H>>>(hidden, W, bias);
    k_convB<<<(H * D2) / 256, 256>>>(W);

    dim3 gs(H / TILE_N, MDIM / TILE_M);   // (2, 512)
    k_scores<<<gs, NTHREADS, SMEM_ALLOC>>>(enc, wv);

    k_softmax<<<BATCH, 256>>>();

    dim3 gc(SEQ / 256, BATCH);
    k_context<<<gc, 256>>>(enc, out);
}